// round 15
// baseline (speedup 1.0000x reference)
#include <cuda_runtime.h>
#include <cuda_bf16.h>

#define N_NODES 10000
#define N_EDGES 640000
#define D 128
#define BN_EPS 1e-5f

// ---------------- scratch (device globals: no allocations allowed) ----------
// g_counts relies on static zero-init; scan_kernel re-zeroes it each run.
__device__ int   g_counts [N_NODES];
__device__ int   g_offsets[N_NODES + 1];
__device__ int   g_rank   [N_EDGES];
__device__ int2  g_pairs  [N_EDGES];        // (edge_id, src_node) sorted by dst
__device__ uint2 g_nfb    [N_NODES * D / 4];// node_feats in bf16 (4 vals / uint2)
__device__ float g_h0 [N_NODES * D];        // GIN combine output        [10000,128]
__device__ float g_t1 [N_NODES * 2 * D];    // after GEMM1 (raw, pre-BN) [10000,256]
__device__ float g_t2 [N_NODES * D];        // after GEMM2 (raw, pre-BN) [10000,128]
__device__ float g_bnsum[1024];             // [0:512) BN1 sum|sumsq, [512:768) BN2

// ---------------- setup: zero bnsum + nf -> bf16 table -----------------------
__global__ void setup_kernel(const float4* __restrict__ nf4) {
    int i = blockIdx.x * blockDim.x + threadIdx.x;
    if (i < 1024) g_bnsum[i] = 0.0f;
    if (i < N_NODES * D / 4) {
        float4 a = nf4[i];
        __nv_bfloat162 lo = __floats2bfloat162_rn(a.x, a.y);
        __nv_bfloat162 hi = __floats2bfloat162_rn(a.z, a.w);
        uint2 u;
        u.x = *(unsigned*)&lo;
        u.y = *(unsigned*)&hi;
        g_nfb[i] = u;
    }
}

// ---------------- degree histogram; keeps per-edge rank ----------------------
__global__ void hist_kernel(const int4* __restrict__ dst4) {
    int i = blockIdx.x * blockDim.x + threadIdx.x;
    if (i < N_EDGES / 4) {
        int4 d = dst4[i];
        int4 r;
        r.x = atomicAdd(&g_counts[d.x], 1);
        r.y = atomicAdd(&g_counts[d.y], 1);
        r.z = atomicAdd(&g_counts[d.z], 1);
        r.w = atomicAdd(&g_counts[d.w], 1);
        ((int4*)g_rank)[i] = r;
    }
}

// ---------------- single-block exclusive scan; re-zeroes counts --------------
#define SCH 10   // counts per thread (1024 * 10 >= 10000)
__global__ void scan_kernel() {
    __shared__ int wsum[32];
    int tid  = threadIdx.x;
    int lane = tid & 31;
    int wid  = tid >> 5;
    int base = tid * SCH;

    int c[SCH];
    int sum = 0;
    #pragma unroll
    for (int i = 0; i < SCH; i++) {
        int idx = base + i;
        c[i] = (idx < N_NODES) ? g_counts[idx] : 0;
        sum += c[i];
    }
    // re-zero counts for the next run (replay-deterministic invariant)
    #pragma unroll
    for (int i = 0; i < SCH; i++) {
        int idx = base + i;
        if (idx < N_NODES) g_counts[idx] = 0;
    }
    // warp inclusive scan of thread sums
    int inc = sum;
    #pragma unroll
    for (int off = 1; off < 32; off <<= 1) {
        int v = __shfl_up_sync(0xFFFFFFFFu, inc, off);
        if (lane >= off) inc += v;
    }
    if (lane == 31) wsum[wid] = inc;
    __syncthreads();
    if (wid == 0) {
        int v = wsum[lane];
        int winc = v;
        #pragma unroll
        for (int off = 1; off < 32; off <<= 1) {
            int t = __shfl_up_sync(0xFFFFFFFFu, winc, off);
            if (lane >= off) winc += t;
        }
        wsum[lane] = winc - v;   // exclusive warp prefix
    }
    __syncthreads();
    int run = wsum[wid] + (inc - sum);   // exclusive prefix for this thread
    #pragma unroll
    for (int i = 0; i < SCH; i++) {
        int idx = base + i;
        if (idx < N_NODES) g_offsets[idx] = run;
        run += c[i];
    }
    if (tid == 1023) g_offsets[N_NODES] = run;
}

// ---------------- scatter (atomic-free): pairs[off[d]+rank] = (e, src) -------
__global__ void scatter_kernel(const int4* __restrict__ dst4,
                               const int4* __restrict__ src4) {
    int i = blockIdx.x * blockDim.x + threadIdx.x;
    if (i < N_EDGES / 4) {
        int4 d = dst4[i];
        int4 r = __ldg((const int4*)g_rank + i);
        int4 s = src4[i];
        int e = i * 4;
        g_pairs[__ldg(&g_offsets[d.x]) + r.x] = make_int2(e,     s.x);
        g_pairs[__ldg(&g_offsets[d.y]) + r.y] = make_int2(e + 1, s.y);
        g_pairs[__ldg(&g_offsets[d.z]) + r.z] = make_int2(e + 2, s.z);
        g_pairs[__ldg(&g_offsets[d.w]) + r.w] = make_int2(e + 3, s.w);
    }
}

// ---------------- per-node aggregation (one warp per node, unroll x8) --------
// nf gathered as bf16 (half the LTS bytes); self term stays exact fp32.
__global__ void aggregate_kernel(const float* __restrict__ nf,
                                 const float* __restrict__ ef,
                                 const float* __restrict__ eps) {
    int gw   = (blockIdx.x * blockDim.x + threadIdx.x) >> 5;
    int lane = threadIdx.x & 31;
    if (gw >= N_NODES) return;
    int beg = g_offsets[gw], end = g_offsets[gw + 1];

    float4 acc0 = make_float4(0.f, 0.f, 0.f, 0.f);
    float4 acc1 = make_float4(0.f, 0.f, 0.f, 0.f);
    float4 acc2 = make_float4(0.f, 0.f, 0.f, 0.f);
    float4 acc3 = make_float4(0.f, 0.f, 0.f, 0.f);

    #define NFB_LOAD(p)  __ldg(&g_nfb[(size_t)(p).y * (D / 4) + lane])
    #define ACC(acc, u, b)  do {                                               \
        float2 _lo = __bfloat1622float2(*(__nv_bfloat162*)&(u).x);             \
        float2 _hi = __bfloat1622float2(*(__nv_bfloat162*)&(u).y);             \
        (acc).x += _lo.x + (b).x; (acc).y += _lo.y + (b).y;                    \
        (acc).z += _hi.x + (b).z; (acc).w += _hi.y + (b).w;                    \
    } while (0)

    int i = beg;
    for (; i + 8 <= end; i += 8) {
        int2 p0 = g_pairs[i],     p1 = g_pairs[i + 1];
        int2 p2 = g_pairs[i + 2], p3 = g_pairs[i + 3];
        int2 p4 = g_pairs[i + 4], p5 = g_pairs[i + 5];
        int2 p6 = g_pairs[i + 6], p7 = g_pairs[i + 7];
        float4 b0 = __ldcs((const float4*)(ef + (size_t)p0.x * D) + lane);
        float4 b1 = __ldcs((const float4*)(ef + (size_t)p1.x * D) + lane);
        float4 b2 = __ldcs((const float4*)(ef + (size_t)p2.x * D) + lane);
        float4 b3 = __ldcs((const float4*)(ef + (size_t)p3.x * D) + lane);
        float4 b4 = __ldcs((const float4*)(ef + (size_t)p4.x * D) + lane);
        float4 b5 = __ldcs((const float4*)(ef + (size_t)p5.x * D) + lane);
        float4 b6 = __ldcs((const float4*)(ef + (size_t)p6.x * D) + lane);
        float4 b7 = __ldcs((const float4*)(ef + (size_t)p7.x * D) + lane);
        uint2 a0 = NFB_LOAD(p0);
        uint2 a1 = NFB_LOAD(p1);
        uint2 a2 = NFB_LOAD(p2);
        uint2 a3 = NFB_LOAD(p3);
        uint2 a4 = NFB_LOAD(p4);
        uint2 a5 = NFB_LOAD(p5);
        uint2 a6 = NFB_LOAD(p6);
        uint2 a7 = NFB_LOAD(p7);
        ACC(acc0, a0, b0);
        ACC(acc1, a1, b1);
        ACC(acc2, a2, b2);
        ACC(acc3, a3, b3);
        ACC(acc0, a4, b4);
        ACC(acc1, a5, b5);
        ACC(acc2, a6, b6);
        ACC(acc3, a7, b7);
    }
    for (; i < end; i++) {
        int2 p0 = g_pairs[i];
        float4 b0 = __ldcs((const float4*)(ef + (size_t)p0.x * D) + lane);
        uint2 a0 = NFB_LOAD(p0);
        ACC(acc0, a0, b0);
    }
    float cnt = (float)(end - beg);
    float inv = 1.0f / fmaxf(cnt, 1.0f);
    float sc  = 1.0f + eps[0];
    float4 m  = ((const float4*)(nf + (size_t)gw * D))[lane];
    float4 o;
    o.x = sc * m.x + (acc0.x + acc1.x + acc2.x + acc3.x) * inv;
    o.y = sc * m.y + (acc0.y + acc1.y + acc2.y + acc3.y) * inv;
    o.z = sc * m.z + (acc0.z + acc1.z + acc2.z + acc3.z) * inv;
    o.w = sc * m.w + (acc0.w + acc1.w + acc2.w + acc3.w) * inv;
    ((float4*)(g_h0 + (size_t)gw * D))[lane] = o;
}

// ---------------- tf32 tensor-core GEMM (proven R9 version) ------------------
#define BM 128
#define BN_T 64
#define BK 16
#define AS_STRIDE 136
#define BS_STRIDE 72

__device__ __forceinline__ unsigned f2tf32(float x) {
    unsigned r;
    asm("cvt.rna.tf32.f32 %0, %1;" : "=r"(r) : "f"(x));
    return r;
}

#define MMA_TF32(C, A, B)                                                      \
    asm volatile("mma.sync.aligned.m16n8k8.row.col.f32.tf32.tf32.f32 "         \
                 "{%0,%1,%2,%3}, {%4,%5,%6,%7}, {%8,%9}, {%0,%1,%2,%3};"       \
                 : "+f"((C)[0]), "+f"((C)[1]), "+f"((C)[2]), "+f"((C)[3])      \
                 : "r"((A)[0]), "r"((A)[1]), "r"((A)[2]), "r"((A)[3]),         \
                   "r"((B)[0]), "r"((B)[1]))

template <bool BN_IN>
__global__ __launch_bounds__(256) void gemm_tf32_fused(
    const float* __restrict__ A, const float* __restrict__ B,
    const float* __restrict__ bias, float* __restrict__ C,
    int M, int N, int K,
    const float* __restrict__ bn_sums,
    const float* __restrict__ bn_gamma,
    const float* __restrict__ bn_beta,
    float* __restrict__ bn_out)
{
    __shared__ union {
        struct {
            unsigned As[BK * AS_STRIDE];
            unsigned Bs[BK * BS_STRIDE];
        } t;
        float red[2 * 32 * BN_T];
    } sm;
    __shared__ float s_scl[256];
    __shared__ float s_sh [256];

    int tid  = threadIdx.x;
    int lane = tid & 31;
    int q    = lane & 3;
    int g    = lane >> 2;
    int wid  = tid >> 5;
    int wm   = wid & 3;
    int wn   = wid >> 2;
    int bm   = blockIdx.y * BM;
    int bn   = blockIdx.x * BN_T;

    if (BN_IN) {
        float invM = 1.0f / (float)M;
        for (int c = tid; c < K; c += 256) {
            float mean = bn_sums[c] * invM;
            float var  = bn_sums[K + c] * invM - mean * mean;
            float scl  = bn_gamma[c] * rsqrtf(var + BN_EPS);
            s_scl[c] = scl;
            s_sh [c] = bn_beta[c] - mean * scl;
        }
        __syncthreads();
    }

    float acc[2][4][4];
    #pragma unroll
    for (int mt = 0; mt < 2; mt++)
        #pragma unroll
        for (int nt = 0; nt < 4; nt++)
            #pragma unroll
            for (int j = 0; j < 4; j++) acc[mt][nt][j] = 0.f;

    int arow0 = tid >> 2;
    int arow1 = (tid + 256) >> 2;
    int akc   = (tid & 3) * 4;
    int bkr = tid >> 4;
    int bnc = (tid & 15) * 4;

    for (int k0 = 0; k0 < K; k0 += BK) {
        #pragma unroll
        for (int t = 0; t < 2; t++) {
            int row = t ? arow1 : arow0;
            int gr  = bm + row;
            float4 a = make_float4(0.f, 0.f, 0.f, 0.f);
            if (gr < M) {
                a = *(const float4*)(A + (size_t)gr * K + k0 + akc);
                if (BN_IN) {
                    int c = k0 + akc;
                    a.x = fmaxf(fmaf(a.x, s_scl[c + 0], s_sh[c + 0]), 0.f);
                    a.y = fmaxf(fmaf(a.y, s_scl[c + 1], s_sh[c + 1]), 0.f);
                    a.z = fmaxf(fmaf(a.z, s_scl[c + 2], s_sh[c + 2]), 0.f);
                    a.w = fmaxf(fmaf(a.w, s_scl[c + 3], s_sh[c + 3]), 0.f);
                }
            }
            sm.t.As[(akc + 0) * AS_STRIDE + row] = f2tf32(a.x);
            sm.t.As[(akc + 1) * AS_STRIDE + row] = f2tf32(a.y);
            sm.t.As[(akc + 2) * AS_STRIDE + row] = f2tf32(a.z);
            sm.t.As[(akc + 3) * AS_STRIDE + row] = f2tf32(a.w);
        }
        {
            float4 b = *(const float4*)(B + (size_t)(k0 + bkr) * N + bn + bnc);
            sm.t.Bs[bkr * BS_STRIDE + bnc + 0] = f2tf32(b.x);
            sm.t.Bs[bkr * BS_STRIDE + bnc + 1] = f2tf32(b.y);
            sm.t.Bs[bkr * BS_STRIDE + bnc + 2] = f2tf32(b.z);
            sm.t.Bs[bkr * BS_STRIDE + bnc + 3] = f2tf32(b.w);
        }
        __syncthreads();

        #pragma unroll
        for (int ks = 0; ks < BK; ks += 8) {
            unsigned afr[2][4], bfr[4][2];
            int kq = ks + q;
            #pragma unroll
            for (int mt = 0; mt < 2; mt++) {
                int m = wm * 32 + mt * 16 + g;
                afr[mt][0] = sm.t.As[kq * AS_STRIDE + m];
                afr[mt][1] = sm.t.As[kq * AS_STRIDE + m + 8];
                afr[mt][2] = sm.t.As[(kq + 4) * AS_STRIDE + m];
                afr[mt][3] = sm.t.As[(kq + 4) * AS_STRIDE + m + 8];
            }
            #pragma unroll
            for (int nt = 0; nt < 4; nt++) {
                int n = wn * 32 + nt * 8 + g;
                bfr[nt][0] = sm.t.Bs[kq * BS_STRIDE + n];
                bfr[nt][1] = sm.t.Bs[(kq + 4) * BS_STRIDE + n];
            }
            #pragma unroll
            for (int mt = 0; mt < 2; mt++)
                #pragma unroll
                for (int nt = 0; nt < 4; nt++)
                    MMA_TF32(acc[mt][nt], afr[mt], bfr[nt]);
        }
        __syncthreads();
    }

    float psum[8], psq[8];
    #pragma unroll
    for (int j = 0; j < 8; j++) { psum[j] = 0.f; psq[j] = 0.f; }

    #pragma unroll
    for (int nt = 0; nt < 4; nt++) {
        int gc = bn + wn * 32 + nt * 8 + 2 * q;
        float b0 = bias[gc], b1 = bias[gc + 1];
        #pragma unroll
        for (int mt = 0; mt < 2; mt++) {
            int r0 = bm + wm * 32 + mt * 16 + g;
            if (r0 < M) {
                float v0 = acc[mt][nt][0] + b0;
                float v1 = acc[mt][nt][1] + b1;
                *(float2*)(C + (size_t)r0 * N + gc) = make_float2(v0, v1);
                psum[nt * 2]     += v0;  psq[nt * 2]     += v0 * v0;
                psum[nt * 2 + 1] += v1;  psq[nt * 2 + 1] += v1 * v1;
            }
            int r1 = r0 + 8;
            if (r1 < M) {
                float v2 = acc[mt][nt][2] + b0;
                float v3 = acc[mt][nt][3] + b1;
                *(float2*)(C + (size_t)r1 * N + gc) = make_float2(v2, v3);
                psum[nt * 2]     += v2;  psq[nt * 2]     += v2 * v2;
                psum[nt * 2 + 1] += v3;  psq[nt * 2 + 1] += v3 * v3;
            }
        }
    }
    __syncthreads();
    int slot = wm * 8 + g;
    #pragma unroll
    for (int nt = 0; nt < 4; nt++) {
        int cl = wn * 32 + nt * 8 + 2 * q;
        sm.red[slot * BN_T + cl]            = psum[nt * 2];
        sm.red[slot * BN_T + cl + 1]        = psum[nt * 2 + 1];
        sm.red[2048 + slot * BN_T + cl]     = psq[nt * 2];
        sm.red[2048 + slot * BN_T + cl + 1] = psq[nt * 2 + 1];
    }
    __syncthreads();
    if (tid < BN_T) {
        float s = 0.f, s2 = 0.f;
        #pragma unroll
        for (int t = 0; t < 32; t++) {
            s  += sm.red[t * BN_T + tid];
            s2 += sm.red[2048 + t * BN_T + tid];
        }
        atomicAdd(&bn_out[bn + tid],     s);
        atomicAdd(&bn_out[N + bn + tid], s2);
    }
}

// ---------------- BN apply + ReLU (vectorized float4) ------------------------
__global__ void bn_apply(const float4* __restrict__ x, float4* __restrict__ y,
                         const float* __restrict__ sums,
                         const float* __restrict__ gamma,
                         const float* __restrict__ beta, int M, int C) {
    int idx = blockIdx.x * blockDim.x + threadIdx.x;
    int total = M * C / 4;
    if (idx >= total) return;
    int col = (idx * 4) % C;
    float invM = 1.0f / (float)M;
    float4 v = x[idx];
    float4 o;
    #pragma unroll
    for (int j = 0; j < 4; j++) {
        int c = col + j;
        float mean = sums[c] * invM;
        float var  = sums[C + c] * invM - mean * mean;
        float scl = gamma[c] * rsqrtf(var + BN_EPS);
        float sh  = beta[c] - mean * scl;
        float val = (&v.x)[j] * scl + sh;
        (&o.x)[j] = fmaxf(val, 0.f);
    }
    y[idx] = o;
}

// ---------------- launch ------------------------------------------------------
extern "C" void kernel_launch(void* const* d_in, const int* in_sizes, int n_in,
                              void* d_out, int out_size) {
    const float* nf  = (const float*)d_in[0];   // node_feats [10000,128]
    const float* ef  = (const float*)d_in[1];   // edge_feats [640000,128]
    const float* eps = (const float*)d_in[2];   // eps [1]
    const float* W1  = (const float*)d_in[3];   // [128,256]
    const float* b1  = (const float*)d_in[4];   // [256]
    const float* g1  = (const float*)d_in[5];   // [256]
    const float* be1 = (const float*)d_in[6];   // [256]
    const float* W2  = (const float*)d_in[7];   // [256,128]
    const float* b2  = (const float*)d_in[8];   // [128]
    const float* g2  = (const float*)d_in[9];   // [128]
    const float* be2 = (const float*)d_in[10];  // [128]
    const int*   src = (const int*)d_in[11];    // [640000]
    const int*   dst = (const int*)d_in[12];    // [640000]
    float* out = (float*)d_out;                 // [10000,128]

    float *h0, *t1, *t2, *bnsum;
    cudaGetSymbolAddress((void**)&h0,    g_h0);
    cudaGetSymbolAddress((void**)&t1,    g_t1);
    cudaGetSymbolAddress((void**)&t2,    g_t2);
    cudaGetSymbolAddress((void**)&bnsum, g_bnsum);

    setup_kernel  <<<(N_NODES * D / 4 + 255) / 256, 256>>>((const float4*)nf);
    hist_kernel   <<<(N_EDGES / 4 + 255) / 256, 256>>>((const int4*)dst);
    scan_kernel   <<<1, 1024>>>();
    scatter_kernel<<<(N_EDGES / 4 + 255) / 256, 256>>>((const int4*)dst,
                                                       (const int4*)src);
    aggregate_kernel<<<(N_NODES * 32 + 255) / 256, 256>>>(nf, ef, eps);

    // GEMM1: h0 @ W1 + b1 -> t1 (raw); epilogue accumulates BN1 stats
    {
        dim3 grid(2 * D / BN_T, (N_NODES + BM - 1) / BM);    // (4, 79)
        gemm_tf32_fused<false><<<grid, 256>>>(h0, W1, b1, t1, N_NODES, 2 * D, D,
                                              nullptr, nullptr, nullptr, bnsum);
    }
    // GEMM2: relu(BN1(t1)) @ W2 + b2 -> t2 (raw); epilogue accumulates BN2 stats
    {
        dim3 grid(D / BN_T, (N_NODES + BM - 1) / BM);        // (2, 79)
        gemm_tf32_fused<true><<<grid, 256>>>(t1, W2, b2, t2, N_NODES, D, 2 * D,
                                             bnsum, g1, be1, bnsum + 512);
    }
    // BN2 apply + ReLU -> out
    bn_apply<<<(N_NODES * D / 4 + 255) / 256, 256>>>((const float4*)t2,
                                                     (float4*)out, bnsum + 512,
                                                     g2, be2, N_NODES, D);
}

// round 16
// speedup vs baseline: 1.0978x; 1.0978x over previous
#include <cuda_runtime.h>
#include <cuda_bf16.h>

#define N_NODES 10000
#define N_EDGES 640000
#define D 128
#define BN_EPS 1e-5f

// ---------------- scratch (device globals: no allocations allowed) ----------
__device__ int   g_counts [N_NODES];
__device__ int   g_offsets[N_NODES + 1];
__device__ int   g_rank   [N_EDGES];
__device__ int2  g_pairs  [N_EDGES];        // (edge_id, src_node) sorted by dst
__device__ uint2 g_nfb    [N_NODES * D / 4];// node_feats in bf16 (4 vals / uint2)
__device__ float g_h0 [N_NODES * D];        // GIN combine output        [10000,128]
__device__ float g_t1 [N_NODES * 2 * D];    // after GEMM1 (raw, pre-BN) [10000,256]
__device__ float g_t2 [N_NODES * D];        // after GEMM2 (raw, pre-BN) [10000,128]
__device__ float g_bnsum[1024];             // [0:512) BN1 sum|sumsq, [512:768) BN2

// ---------------- setup: zero counters/bnsum + nf -> bf16 table --------------
__global__ void setup_kernel(const float4* __restrict__ nf4) {
    int i = blockIdx.x * blockDim.x + threadIdx.x;
    if (i < N_NODES) g_counts[i] = 0;
    if (i < 1024)    g_bnsum[i] = 0.0f;
    if (i < N_NODES * D / 4) {
        float4 a = nf4[i];
        __nv_bfloat162 lo = __floats2bfloat162_rn(a.x, a.y);
        __nv_bfloat162 hi = __floats2bfloat162_rn(a.z, a.w);
        uint2 u;
        u.x = *(unsigned*)&lo;
        u.y = *(unsigned*)&hi;
        g_nfb[i] = u;
    }
}

// ---------------- degree histogram; keeps per-edge rank ----------------------
__global__ void hist_kernel(const int4* __restrict__ dst4) {
    int i = blockIdx.x * blockDim.x + threadIdx.x;
    if (i < N_EDGES / 4) {
        int4 d = dst4[i];
        int4 r;
        r.x = atomicAdd(&g_counts[d.x], 1);
        r.y = atomicAdd(&g_counts[d.y], 1);
        r.z = atomicAdd(&g_counts[d.z], 1);
        r.w = atomicAdd(&g_counts[d.w], 1);
        ((int4*)g_rank)[i] = r;
    }
}

// ---------------- single-block exclusive scan (shuffle-based, 2 barriers) ----
#define SCH 10   // counts per thread (1024 * 10 >= 10000)
__global__ void scan_kernel() {
    __shared__ int wsum[32];
    int tid  = threadIdx.x;
    int lane = tid & 31;
    int wid  = tid >> 5;
    int base = tid * SCH;

    int c[SCH];
    int sum = 0;
    #pragma unroll
    for (int i = 0; i < SCH; i++) {
        int idx = base + i;
        c[i] = (idx < N_NODES) ? g_counts[idx] : 0;
        sum += c[i];
    }
    // warp inclusive scan of thread sums
    int inc = sum;
    #pragma unroll
    for (int off = 1; off < 32; off <<= 1) {
        int v = __shfl_up_sync(0xFFFFFFFFu, inc, off);
        if (lane >= off) inc += v;
    }
    if (lane == 31) wsum[wid] = inc;
    __syncthreads();
    if (wid == 0) {
        int v = wsum[lane];
        int winc = v;
        #pragma unroll
        for (int off = 1; off < 32; off <<= 1) {
            int t = __shfl_up_sync(0xFFFFFFFFu, winc, off);
            if (lane >= off) winc += t;
        }
        wsum[lane] = winc - v;   // exclusive warp prefix
    }
    __syncthreads();
    int run = wsum[wid] + (inc - sum);   // exclusive prefix for this thread
    #pragma unroll
    for (int i = 0; i < SCH; i++) {
        int idx = base + i;
        if (idx < N_NODES) g_offsets[idx] = run;
        run += c[i];
    }
    if (tid == 1023) g_offsets[N_NODES] = run;
}

// ---------------- scatter (atomic-free): pairs[off[d]+rank] = (e, src) -------
__global__ void scatter_kernel(const int4* __restrict__ dst4,
                               const int4* __restrict__ src4) {
    int i = blockIdx.x * blockDim.x + threadIdx.x;
    if (i < N_EDGES / 4) {
        int4 d = dst4[i];
        int4 r = __ldg((const int4*)g_rank + i);
        int4 s = src4[i];
        int e = i * 4;
        g_pairs[__ldg(&g_offsets[d.x]) + r.x] = make_int2(e,     s.x);
        g_pairs[__ldg(&g_offsets[d.y]) + r.y] = make_int2(e + 1, s.y);
        g_pairs[__ldg(&g_offsets[d.z]) + r.z] = make_int2(e + 2, s.z);
        g_pairs[__ldg(&g_offsets[d.w]) + r.w] = make_int2(e + 3, s.w);
    }
}

// ---------------- per-node aggregation (one warp per node, unroll x4) --------
// nf gathered as bf16 (half the LTS bytes); self term stays exact fp32.
// Pair indices loaded two-at-a-time (int4 = 2 int2 pairs) to halve index LDGs.
__global__ void aggregate_kernel(const float* __restrict__ nf,
                                 const float* __restrict__ ef,
                                 const float* __restrict__ eps) {
    int gw   = (blockIdx.x * blockDim.x + threadIdx.x) >> 5;
    int lane = threadIdx.x & 31;
    if (gw >= N_NODES) return;
    int beg = g_offsets[gw], end = g_offsets[gw + 1];

    float4 acc0 = make_float4(0.f, 0.f, 0.f, 0.f);
    float4 acc1 = make_float4(0.f, 0.f, 0.f, 0.f);
    float4 acc2 = make_float4(0.f, 0.f, 0.f, 0.f);
    float4 acc3 = make_float4(0.f, 0.f, 0.f, 0.f);

    #define NFB_LOAD_I(sidx)  g_nfb[(size_t)(sidx) * (D / 4) + lane]
    #define ACC(acc, u, b)  do {                                               \
        float2 _lo = __bfloat1622float2(*(__nv_bfloat162*)&(u).x);             \
        float2 _hi = __bfloat1622float2(*(__nv_bfloat162*)&(u).y);             \
        (acc).x += _lo.x + (b).x; (acc).y += _lo.y + (b).y;                    \
        (acc).z += _hi.x + (b).z; (acc).w += _hi.y + (b).w;                    \
    } while (0)

    int i = beg;
    // aligned int4 fast path requires even index; peel one pair if beg is odd
    if ((i & 1) && i < end) {
        int2 p0 = g_pairs[i];
        float4 b0 = __ldcs((const float4*)(ef + (size_t)p0.x * D) + lane);
        uint2 a0 = NFB_LOAD_I(p0.y);
        ACC(acc0, a0, b0);
        i++;
    }
    for (; i + 4 <= end; i += 4) {
        int4 q0 = *(const int4*)&g_pairs[i];       // (e0, s0, e1, s1)
        int4 q1 = *(const int4*)&g_pairs[i + 2];   // (e2, s2, e3, s3)
        float4 b0 = __ldcs((const float4*)(ef + (size_t)q0.x * D) + lane);
        float4 b1 = __ldcs((const float4*)(ef + (size_t)q0.z * D) + lane);
        float4 b2 = __ldcs((const float4*)(ef + (size_t)q1.x * D) + lane);
        float4 b3 = __ldcs((const float4*)(ef + (size_t)q1.z * D) + lane);
        uint2 a0 = NFB_LOAD_I(q0.y);
        uint2 a1 = NFB_LOAD_I(q0.w);
        uint2 a2 = NFB_LOAD_I(q1.y);
        uint2 a3 = NFB_LOAD_I(q1.w);
        ACC(acc0, a0, b0);
        ACC(acc1, a1, b1);
        ACC(acc2, a2, b2);
        ACC(acc3, a3, b3);
    }
    for (; i < end; i++) {
        int2 p0 = g_pairs[i];
        float4 b0 = __ldcs((const float4*)(ef + (size_t)p0.x * D) + lane);
        uint2 a0 = NFB_LOAD_I(p0.y);
        ACC(acc0, a0, b0);
    }
    float cnt = (float)(end - beg);
    float inv = 1.0f / fmaxf(cnt, 1.0f);
    float sc  = 1.0f + eps[0];
    float4 m  = ((const float4*)(nf + (size_t)gw * D))[lane];
    float4 o;
    o.x = sc * m.x + (acc0.x + acc1.x + acc2.x + acc3.x) * inv;
    o.y = sc * m.y + (acc0.y + acc1.y + acc2.y + acc3.y) * inv;
    o.z = sc * m.z + (acc0.z + acc1.z + acc2.z + acc3.z) * inv;
    o.w = sc * m.w + (acc0.w + acc1.w + acc2.w + acc3.w) * inv;
    ((float4*)(g_h0 + (size_t)gw * D))[lane] = o;
}

// ---------------- tf32 tensor-core GEMM (proven R9 version) ------------------
#define BM 128
#define BN_T 64
#define BK 16
#define AS_STRIDE 136
#define BS_STRIDE 72

__device__ __forceinline__ unsigned f2tf32(float x) {
    unsigned r;
    asm("cvt.rna.tf32.f32 %0, %1;" : "=r"(r) : "f"(x));
    return r;
}

#define MMA_TF32(C, A, B)                                                      \
    asm volatile("mma.sync.aligned.m16n8k8.row.col.f32.tf32.tf32.f32 "         \
                 "{%0,%1,%2,%3}, {%4,%5,%6,%7}, {%8,%9}, {%0,%1,%2,%3};"       \
                 : "+f"((C)[0]), "+f"((C)[1]), "+f"((C)[2]), "+f"((C)[3])      \
                 : "r"((A)[0]), "r"((A)[1]), "r"((A)[2]), "r"((A)[3]),         \
                   "r"((B)[0]), "r"((B)[1]))

template <bool BN_IN>
__global__ __launch_bounds__(256) void gemm_tf32_fused(
    const float* __restrict__ A, const float* __restrict__ B,
    const float* __restrict__ bias, float* __restrict__ C,
    int M, int N, int K,
    const float* __restrict__ bn_sums,
    const float* __restrict__ bn_gamma,
    const float* __restrict__ bn_beta,
    float* __restrict__ bn_out)
{
    __shared__ union {
        struct {
            unsigned As[BK * AS_STRIDE];
            unsigned Bs[BK * BS_STRIDE];
        } t;
        float red[2 * 32 * BN_T];
    } sm;
    __shared__ float s_scl[256];
    __shared__ float s_sh [256];

    int tid  = threadIdx.x;
    int lane = tid & 31;
    int q    = lane & 3;
    int g    = lane >> 2;
    int wid  = tid >> 5;
    int wm   = wid & 3;
    int wn   = wid >> 2;
    int bm   = blockIdx.y * BM;
    int bn   = blockIdx.x * BN_T;

    if (BN_IN) {
        float invM = 1.0f / (float)M;
        for (int c = tid; c < K; c += 256) {
            float mean = bn_sums[c] * invM;
            float var  = bn_sums[K + c] * invM - mean * mean;
            float scl  = bn_gamma[c] * rsqrtf(var + BN_EPS);
            s_scl[c] = scl;
            s_sh [c] = bn_beta[c] - mean * scl;
        }
        __syncthreads();
    }

    float acc[2][4][4];
    #pragma unroll
    for (int mt = 0; mt < 2; mt++)
        #pragma unroll
        for (int nt = 0; nt < 4; nt++)
            #pragma unroll
            for (int j = 0; j < 4; j++) acc[mt][nt][j] = 0.f;

    int arow0 = tid >> 2;
    int arow1 = (tid + 256) >> 2;
    int akc   = (tid & 3) * 4;
    int bkr = tid >> 4;
    int bnc = (tid & 15) * 4;

    for (int k0 = 0; k0 < K; k0 += BK) {
        #pragma unroll
        for (int t = 0; t < 2; t++) {
            int row = t ? arow1 : arow0;
            int gr  = bm + row;
            float4 a = make_float4(0.f, 0.f, 0.f, 0.f);
            if (gr < M) {
                a = *(const float4*)(A + (size_t)gr * K + k0 + akc);
                if (BN_IN) {
                    int c = k0 + akc;
                    a.x = fmaxf(fmaf(a.x, s_scl[c + 0], s_sh[c + 0]), 0.f);
                    a.y = fmaxf(fmaf(a.y, s_scl[c + 1], s_sh[c + 1]), 0.f);
                    a.z = fmaxf(fmaf(a.z, s_scl[c + 2], s_sh[c + 2]), 0.f);
                    a.w = fmaxf(fmaf(a.w, s_scl[c + 3], s_sh[c + 3]), 0.f);
                }
            }
            sm.t.As[(akc + 0) * AS_STRIDE + row] = f2tf32(a.x);
            sm.t.As[(akc + 1) * AS_STRIDE + row] = f2tf32(a.y);
            sm.t.As[(akc + 2) * AS_STRIDE + row] = f2tf32(a.z);
            sm.t.As[(akc + 3) * AS_STRIDE + row] = f2tf32(a.w);
        }
        {
            float4 b = *(const float4*)(B + (size_t)(k0 + bkr) * N + bn + bnc);
            sm.t.Bs[bkr * BS_STRIDE + bnc + 0] = f2tf32(b.x);
            sm.t.Bs[bkr * BS_STRIDE + bnc + 1] = f2tf32(b.y);
            sm.t.Bs[bkr * BS_STRIDE + bnc + 2] = f2tf32(b.z);
            sm.t.Bs[bkr * BS_STRIDE + bnc + 3] = f2tf32(b.w);
        }
        __syncthreads();

        #pragma unroll
        for (int ks = 0; ks < BK; ks += 8) {
            unsigned afr[2][4], bfr[4][2];
            int kq = ks + q;
            #pragma unroll
            for (int mt = 0; mt < 2; mt++) {
                int m = wm * 32 + mt * 16 + g;
                afr[mt][0] = sm.t.As[kq * AS_STRIDE + m];
                afr[mt][1] = sm.t.As[kq * AS_STRIDE + m + 8];
                afr[mt][2] = sm.t.As[(kq + 4) * AS_STRIDE + m];
                afr[mt][3] = sm.t.As[(kq + 4) * AS_STRIDE + m + 8];
            }
            #pragma unroll
            for (int nt = 0; nt < 4; nt++) {
                int n = wn * 32 + nt * 8 + g;
                bfr[nt][0] = sm.t.Bs[kq * BS_STRIDE + n];
                bfr[nt][1] = sm.t.Bs[(kq + 4) * BS_STRIDE + n];
            }
            #pragma unroll
            for (int mt = 0; mt < 2; mt++)
                #pragma unroll
                for (int nt = 0; nt < 4; nt++)
                    MMA_TF32(acc[mt][nt], afr[mt], bfr[nt]);
        }
        __syncthreads();
    }

    float psum[8], psq[8];
    #pragma unroll
    for (int j = 0; j < 8; j++) { psum[j] = 0.f; psq[j] = 0.f; }

    #pragma unroll
    for (int nt = 0; nt < 4; nt++) {
        int gc = bn + wn * 32 + nt * 8 + 2 * q;
        float b0 = bias[gc], b1 = bias[gc + 1];
        #pragma unroll
        for (int mt = 0; mt < 2; mt++) {
            int r0 = bm + wm * 32 + mt * 16 + g;
            if (r0 < M) {
                float v0 = acc[mt][nt][0] + b0;
                float v1 = acc[mt][nt][1] + b1;
                *(float2*)(C + (size_t)r0 * N + gc) = make_float2(v0, v1);
                psum[nt * 2]     += v0;  psq[nt * 2]     += v0 * v0;
                psum[nt * 2 + 1] += v1;  psq[nt * 2 + 1] += v1 * v1;
            }
            int r1 = r0 + 8;
            if (r1 < M) {
                float v2 = acc[mt][nt][2] + b0;
                float v3 = acc[mt][nt][3] + b1;
                *(float2*)(C + (size_t)r1 * N + gc) = make_float2(v2, v3);
                psum[nt * 2]     += v2;  psq[nt * 2]     += v2 * v2;
                psum[nt * 2 + 1] += v3;  psq[nt * 2 + 1] += v3 * v3;
            }
        }
    }
    __syncthreads();
    int slot = wm * 8 + g;
    #pragma unroll
    for (int nt = 0; nt < 4; nt++) {
        int cl = wn * 32 + nt * 8 + 2 * q;
        sm.red[slot * BN_T + cl]            = psum[nt * 2];
        sm.red[slot * BN_T + cl + 1]        = psum[nt * 2 + 1];
        sm.red[2048 + slot * BN_T + cl]     = psq[nt * 2];
        sm.red[2048 + slot * BN_T + cl + 1] = psq[nt * 2 + 1];
    }
    __syncthreads();
    if (tid < BN_T) {
        float s = 0.f, s2 = 0.f;
        #pragma unroll
        for (int t = 0; t < 32; t++) {
            s  += sm.red[t * BN_T + tid];
            s2 += sm.red[2048 + t * BN_T + tid];
        }
        atomicAdd(&bn_out[bn + tid],     s);
        atomicAdd(&bn_out[N + bn + tid], s2);
    }
}

// ---------------- BN apply + ReLU (vectorized float4) ------------------------
__global__ void bn_apply(const float4* __restrict__ x, float4* __restrict__ y,
                         const float* __restrict__ sums,
                         const float* __restrict__ gamma,
                         const float* __restrict__ beta, int M, int C) {
    int idx = blockIdx.x * blockDim.x + threadIdx.x;
    int total = M * C / 4;
    if (idx >= total) return;
    int col = (idx * 4) % C;
    float invM = 1.0f / (float)M;
    float4 v = x[idx];
    float4 o;
    #pragma unroll
    for (int j = 0; j < 4; j++) {
        int c = col + j;
        float mean = sums[c] * invM;
        float var  = sums[C + c] * invM - mean * mean;
        float scl = gamma[c] * rsqrtf(var + BN_EPS);
        float sh  = beta[c] - mean * scl;
        float val = (&v.x)[j] * scl + sh;
        (&o.x)[j] = fmaxf(val, 0.f);
    }
    y[idx] = o;
}

// ---------------- launch ------------------------------------------------------
extern "C" void kernel_launch(void* const* d_in, const int* in_sizes, int n_in,
                              void* d_out, int out_size) {
    const float* nf  = (const float*)d_in[0];   // node_feats [10000,128]
    const float* ef  = (const float*)d_in[1];   // edge_feats [640000,128]
    const float* eps = (const float*)d_in[2];   // eps [1]
    const float* W1  = (const float*)d_in[3];   // [128,256]
    const float* b1  = (const float*)d_in[4];   // [256]
    const float* g1  = (const float*)d_in[5];   // [256]
    const float* be1 = (const float*)d_in[6];   // [256]
    const float* W2  = (const float*)d_in[7];   // [256,128]
    const float* b2  = (const float*)d_in[8];   // [128]
    const float* g2  = (const float*)d_in[9];   // [128]
    const float* be2 = (const float*)d_in[10];  // [128]
    const int*   src = (const int*)d_in[11];    // [640000]
    const int*   dst = (const int*)d_in[12];    // [640000]
    float* out = (float*)d_out;                 // [10000,128]

    float *h0, *t1, *t2, *bnsum;
    cudaGetSymbolAddress((void**)&h0,    g_h0);
    cudaGetSymbolAddress((void**)&t1,    g_t1);
    cudaGetSymbolAddress((void**)&t2,    g_t2);
    cudaGetSymbolAddress((void**)&bnsum, g_bnsum);

    setup_kernel  <<<(N_NODES * D / 4 + 255) / 256, 256>>>((const float4*)nf);
    hist_kernel   <<<(N_EDGES / 4 + 255) / 256, 256>>>((const int4*)dst);
    scan_kernel   <<<1, 1024>>>();
    scatter_kernel<<<(N_EDGES / 4 + 255) / 256, 256>>>((const int4*)dst,
                                                       (const int4*)src);
    aggregate_kernel<<<(N_NODES * 32 + 255) / 256, 256>>>(nf, ef, eps);

    // GEMM1: h0 @ W1 + b1 -> t1 (raw); epilogue accumulates BN1 stats
    {
        dim3 grid(2 * D / BN_T, (N_NODES + BM - 1) / BM);    // (4, 79)
        gemm_tf32_fused<false><<<grid, 256>>>(h0, W1, b1, t1, N_NODES, 2 * D, D,
                                              nullptr, nullptr, nullptr, bnsum);
    }
    // GEMM2: relu(BN1(t1)) @ W2 + b2 -> t2 (raw); epilogue accumulates BN2 stats
    {
        dim3 grid(D / BN_T, (N_NODES + BM - 1) / BM);        // (2, 79)
        gemm_tf32_fused<true><<<grid, 256>>>(t1, W2, b2, t2, N_NODES, D, 2 * D,
                                             bnsum, g1, be1, bnsum + 512);
    }
    // BN2 apply + ReLU -> out
    bn_apply<<<(N_NODES * D / 4 + 255) / 256, 256>>>((const float4*)t2,
                                                     (float4*)out, bnsum + 512,
                                                     g2, be2, N_NODES, D);
}